// round 16
// baseline (speedup 1.0000x reference)
#include <cuda_runtime.h>

#define NN 4096
#define EE 131072
#define CC 32
#define HD 256
#define KD 512
#define ALPHA 0.85f
#define ONEMA (1.0f - 0.85f)
#define EXF (0.85f / 0.15f)
#define EPSV 1e-8f
#define KITER 5
#define NCTA_PROP 128
#define SLOT 96

// ---------------- device scratch ----------------
__device__ float    g_H[NN * HD];
__device__ float    g_F[NN * CC];
__device__ float    g_B[NN * CC];
__device__ float    g_Xa[NN * CC];
__device__ float    g_Xb[NN * CC];
__device__ unsigned g_bitmap[NN * NN / 32];
__device__ float    g_rowsum[NN];   // OFF-DIAGONAL sums only
__device__ int      g_degcnt[NN];   // OFF-DIAGONAL counts only
__device__ float    g_diagv[NN];    // kept diag sim (pre-removediag decision)
__device__ float    g_adeg[NN];
__device__ int      g_rowcnt[NN];   // ELL fill counter
__device__ int      g_ecols[NN * SLOT];
__device__ float    g_evals[NN * SLOT];
__device__ float    g_S00;
__device__ unsigned g_gbar;

// ---------------- packed f32x2 helpers (Blackwell FFMA2) ----------------
__device__ __forceinline__ void ffma2(unsigned long long& d,
                                      unsigned long long a,
                                      unsigned long long b) {
    asm("fma.rn.f32x2 %0, %1, %2, %0;" : "+l"(d) : "l"(a), "l"(b));
}
__device__ __forceinline__ unsigned long long splat2(float x) {
    unsigned long long r;
    asm("mov.b64 %0, {%1, %1};" : "=l"(r) : "r"(__float_as_uint(x)));
    return r;
}
__device__ __forceinline__ void unpack2(unsigned long long v, float& lo, float& hi) {
    unsigned int l, h;
    asm("mov.b64 {%0, %1}, %2;" : "=r"(l), "=r"(h) : "l"(v));
    lo = __uint_as_float(l);
    hi = __uint_as_float(h);
}

// ---------------- GEMM1 (+ fused init): 64x64 tile, 256 CTAs, float4-B + reg-splat ----------------
#define BM 64
#define BN 64
#define BK 16
__global__ __launch_bounds__(256) void k_gemm1(const float* __restrict__ A,
                                               const float* __restrict__ W,
                                               const float* __restrict__ bias) {
    // fused init: 256 CTAs * 256 thr = 65536 threads clear state
    {
        int gid = (blockIdx.y * gridDim.x + blockIdx.x) * 256 + threadIdx.x;
        uint4 z = make_uint4(0u, 0u, 0u, 0u);
        ((uint4*)g_bitmap)[gid]         = z;
        ((uint4*)g_bitmap)[gid + 65536] = z;
        if (gid < NN) {
            g_rowsum[gid] = 0.f;
            g_degcnt[gid] = 0;
            g_diagv[gid]  = 0.f;
            g_adeg[gid]   = 0.f;
            g_rowcnt[gid] = 0;
        }
        if (gid == 0) { g_S00 = 0.f; g_gbar = 0u; }
    }

    __shared__ float As[BK][BM + 4];   // stride 68 floats = 272B (8B-aligned rows)
    __shared__ float Bs[BK][BN];       // stride 256B (16B-aligned rows)
    int tid = threadIdx.x;
    int m0 = blockIdx.x * BM, n0 = blockIdx.y * BN;
    // A loads: 64 rows x 16 k = 1024 floats; 1 float4/thread
    int lm = tid >> 2;             // 0..63
    int lk = (tid & 3) * 4;        // 0,4,8,12
    // B loads: 16 k x 64 n; thread loads 4 consecutive k-rows
    int bn = tid & 63;
    int bk = (tid >> 6) * 4;       // 0,4,8,12
    // compute: 16x16 threads, each 4m x 4n
    int ty = (tid >> 4) * 4;       // m base (multiple of 4, 8B-aligned pairs)
    int tx = (tid & 15) * 4;       // n base (float4-aligned)

    // acc2[mp][j]: m-pair (ty+2mp, ty+2mp+1), column tx+j
    unsigned long long acc2[2][4];
#pragma unroll
    for (int i = 0; i < 2; i++)
#pragma unroll
        for (int j = 0; j < 4; j++) acc2[i][j] = 0ull;

    for (int kk = 0; kk < KD; kk += BK) {
        float4 av = *(const float4*)&A[(size_t)(m0 + lm) * KD + kk + lk];
        As[lk + 0][lm] = av.x;
        As[lk + 1][lm] = av.y;
        As[lk + 2][lm] = av.z;
        As[lk + 3][lm] = av.w;
#pragma unroll
        for (int r = 0; r < 4; r++)
            Bs[bk + r][bn] = W[(size_t)(kk + bk + r) * HD + n0 + bn];
        __syncthreads();
#pragma unroll
        for (int k = 0; k < BK; k++) {
            unsigned long long am0 = *(const unsigned long long*)&As[k][ty];
            unsigned long long am1 = *(const unsigned long long*)&As[k][ty + 2];
            float4 b4 = *(const float4*)&Bs[k][tx];           // 1 LDS.128
            unsigned long long bb0 = splat2(b4.x);            // reg movs, no LDS
            unsigned long long bb1 = splat2(b4.y);
            unsigned long long bb2 = splat2(b4.z);
            unsigned long long bb3 = splat2(b4.w);
            ffma2(acc2[0][0], am0, bb0); ffma2(acc2[1][0], am1, bb0);
            ffma2(acc2[0][1], am0, bb1); ffma2(acc2[1][1], am1, bb1);
            ffma2(acc2[0][2], am0, bb2); ffma2(acc2[1][2], am1, bb2);
            ffma2(acc2[0][3], am0, bb3); ffma2(acc2[1][3], am1, bb3);
        }
        __syncthreads();
    }
    // epilogue: bias + relu, float4 stores (2 rows per m-pair)
    float4 bsv = *(const float4*)&bias[n0 + tx];
#pragma unroll
    for (int mp = 0; mp < 2; mp++) {
        float lo[4], hi[4];
#pragma unroll
        for (int j = 0; j < 4; j++) unpack2(acc2[mp][j], lo[j], hi[j]);
        int m = m0 + ty + 2 * mp;
        float4 v0 = make_float4(fmaxf(lo[0] + bsv.x, 0.f), fmaxf(lo[1] + bsv.y, 0.f),
                                fmaxf(lo[2] + bsv.z, 0.f), fmaxf(lo[3] + bsv.w, 0.f));
        float4 v1 = make_float4(fmaxf(hi[0] + bsv.x, 0.f), fmaxf(hi[1] + bsv.y, 0.f),
                                fmaxf(hi[2] + bsv.z, 0.f), fmaxf(hi[3] + bsv.w, 0.f));
        *(float4*)&g_H[(size_t)m * HD + n0 + tx]       = v0;
        *(float4*)&g_H[(size_t)(m + 1) * HD + n0 + tx] = v1;
    }
}

// ---------------- GEMM2 + normalize ----------------
__global__ __launch_bounds__(1024) void k_gemm2(const float* __restrict__ W1,
                                                const float* __restrict__ b1) {
    int row  = blockIdx.x * 32 + (threadIdx.x >> 5);
    int lane = threadIdx.x & 31;
    const float* h = g_H + (size_t)row * HD;
    float acc = b1[lane];
#pragma unroll 8
    for (int k = 0; k < HD; k++) acc += h[k] * W1[k * CC + lane];
    float sq = acc * acc;
#pragma unroll
    for (int off = 16; off > 0; off >>= 1) sq += __shfl_xor_sync(0xffffffffu, sq, off);
    float nrm = sqrtf(sq);
    float f = acc / fmaxf(nrm, EPSV);
    int o = row * CC + lane;
    g_F[o] = f;
    float bb = ONEMA * acc;
    g_B[o]  = bb;
    g_Xa[o] = bb;
}

// ---------------- barrier primitives ----------------
__device__ __forceinline__ void bar_arrive(unsigned* p) {
    asm volatile("red.add.release.gpu.u32 [%0], 1;" :: "l"(p) : "memory");
}
__device__ __forceinline__ unsigned bar_poll(unsigned* p) {
    unsigned v;
    asm volatile("ld.acquire.gpu.u32 %0, [%1];" : "=r"(v) : "l"(p) : "memory");
    return v;
}

// ---------------- MEGAKERNEL: edges + fill + Jacobi/Richardson ----------------
// 128 CTAs x 1024 thr = 131072 threads = EE; each thread owns one edge.
__global__ __launch_bounds__(1024, 1) void k_prop(const int* __restrict__ row,
                                                  const int* __restrict__ col,
                                                  float* __restrict__ out) {
    __shared__ int   s_cols[32 * SLOT];
    __shared__ float s_vals[32 * SLOT];
    __shared__ volatile int s_epoch;
    int tid  = threadIdx.x;
    int wid  = tid >> 5;
    int lane = tid & 31;
    int gid  = blockIdx.x * 1024 + tid;
    if (tid == 0) s_epoch = 0;
    int ep = 0;

    // ---- phase 1: edge sims + dedup + off-diag row stats ----
    int r = row[gid], c = col[gid];
    float sim;
    {
        const float4* fr = (const float4*)(g_F + r * CC);
        const float4* fc = (const float4*)(g_F + c * CC);
        float4 a0 = fr[0], b0 = fc[0], a1 = fr[1], b1 = fc[1];
        float4 a2 = fr[2], b2 = fc[2], a3 = fr[3], b3 = fc[3];
        float4 a4 = fr[4], b4 = fc[4], a5 = fr[5], b5 = fc[5];
        float4 a6 = fr[6], b6 = fc[6], a7 = fr[7], b7 = fc[7];
        sim = a0.x*b0.x + a0.y*b0.y + a0.z*b0.z + a0.w*b0.w
            + a1.x*b1.x + a1.y*b1.y + a1.z*b1.z + a1.w*b1.w
            + a2.x*b2.x + a2.y*b2.y + a2.z*b2.z + a2.w*b2.w
            + a3.x*b3.x + a3.y*b3.y + a3.z*b3.z + a3.w*b3.w
            + a4.x*b4.x + a4.y*b4.y + a4.z*b4.z + a4.w*b4.w
            + a5.x*b5.x + a5.y*b5.y + a5.z*b5.z + a5.w*b5.w
            + a6.x*b6.x + a6.y*b6.y + a6.z*b6.z + a6.w*b6.w
            + a7.x*b7.x + a7.y*b7.y + a7.z*b7.z + a7.w*b7.w;
    }
    int valid = 0;
    if (sim >= 0.1f) {
        unsigned cell = ((unsigned)r << 12) | (unsigned)c;
        unsigned bit  = 1u << (cell & 31u);
        unsigned old  = atomicOr(&g_bitmap[cell >> 5], bit);
        if (!(old & bit)) {
            valid = 1;
            if (r == c) {
                g_diagv[r] = sim;
                if (cell == 0u) g_S00 = sim;
            } else {
                atomicAdd(&g_rowsum[r], sim);
                atomicAdd(&g_degcnt[r], 1);
            }
        }
    }

    // ---- grid barrier 1 ----
    ep++;
    __syncthreads();
    if (tid == 0) {
        bar_arrive(&g_gbar);
        while (bar_poll(&g_gbar) < (unsigned)(ep * NCTA_PROP)) {}
        s_epoch = ep;
    }
    while (s_epoch < ep) {}

    // ---- phase 2: build ELL ----
    {
        float s00 = g_S00;
        int rd = (s00 == 1.0f);
        int adddiag = rd || !(s00 > 0.f);
        if (valid && !(rd && r == c)) {
            int diag_present = (!rd) && (g_diagv[r] != 0.f);
            float rs = g_rowsum[r] + (diag_present ? g_diagv[r] : 0.f);
            if (rs == 0.f) rs = 1.f;
            float vn = sim / rs;
            if (r == c && adddiag)
                vn += 1.0f / (float)(g_degcnt[r] + diag_present + 1);
            float a = expf(vn);
            int pos = atomicAdd(&g_rowcnt[r], 1);
            g_ecols[r * SLOT + pos] = c;
            g_evals[r * SLOT + pos] = a;
            atomicAdd(&g_adeg[r], a);
        }
        if (gid < NN) {
            int i = gid;
            int diag_present = (!rd) && (g_diagv[i] != 0.f);
            if (adddiag && !diag_present) {
                float a = expf(1.0f / (float)(g_degcnt[i] + 1));
                int pos = atomicAdd(&g_rowcnt[i], 1);
                g_ecols[i * SLOT + pos] = i;
                g_evals[i * SLOT + pos] = a;
                atomicAdd(&g_adeg[i], a);
            }
        }
    }

    // ---- grid barrier 2 ----
    ep++;
    __syncthreads();
    if (tid == 0) {
        bar_arrive(&g_gbar);
        while (bar_poll(&g_gbar) < (unsigned)(ep * NCTA_PROP)) {}
        s_epoch = ep;
    }
    while (s_epoch < ep) {}

    // ---- phase 3: stage ELL in smem, iterate ----
    int prow = blockIdx.x * 32 + wid;
    int cnt = g_rowcnt[prow];
    for (int j = lane; j < cnt; j += 32) {
        s_cols[wid * SLOT + j] = g_ecols[prow * SLOT + j] * CC;
        s_vals[wid * SLOT + j] = g_evals[prow * SLOT + j];
    }
    __syncthreads();

    int base = wid * SLOT;
    int off = prow * CC + lane;
    float bb = g_B[off];
    float sc = ALPHA / fmaxf(g_adeg[prow], EPSV);

    for (int t = 0; t < KITER; t++) {
        const float* __restrict__ X = (t & 1) ? g_Xb : g_Xa;
        float s = 0.f;
#pragma unroll 8
        for (int k = 0; k < cnt; k++)
            s += s_vals[base + k] * __ldcg(X + s_cols[base + k] + lane);
        float xnew = sc * s + bb;
        if (t == KITER - 1) {
            float xprev = __ldcg(X + off);
            out[off] = xnew + EXF * (xnew - xprev);
        } else {
            float* Y = (t & 1) ? g_Xa : g_Xb;
            __stcg(Y + off, xnew);
            ep++;
            __syncthreads();
            if (tid == 0) {
                bar_arrive(&g_gbar);
                while (bar_poll(&g_gbar) < (unsigned)(ep * NCTA_PROP)) {}
                s_epoch = ep;
            }
            while (s_epoch < ep) {}
        }
    }
}

// ---------------- launch (3 launches) ----------------
extern "C" void kernel_launch(void* const* d_in, const int* in_sizes, int n_in,
                              void* d_out, int out_size) {
    const float* attr = (const float*)d_in[0];
    const int*   row  = (const int*)d_in[1];
    const int*   col  = (const int*)d_in[2];
    const float* W0   = (const float*)d_in[3];
    const float* b0   = (const float*)d_in[4];
    const float* W1   = (const float*)d_in[5];
    const float* b1   = (const float*)d_in[6];
    float* out = (float*)d_out;

    k_gemm1<<<dim3(NN / BM, HD / BN), 256>>>(attr, W0, b0);
    k_gemm2<<<NN / 32, 1024>>>(W1, b1);
    k_prop<<<NCTA_PROP, 1024>>>(row, col, out);
}